// round 16
// baseline (speedup 1.0000x reference)
#include <cuda_runtime.h>
#include <cuda_bf16.h>
#include <cuda_fp16.h>
#include <math.h>
#include <stdint.h>

#define B 4
#define L 2048
#define D 1024
#define M_ROWS (B * L)          // 8192
#define NFFT 4096
#define KFS 2080                // row stride for half-spectrum Kf

// ---------------- scratch (static __device__, no allocation) ----------------
__device__ __half g_u16[M_ROWS * 3 * D];     // in_proj output (B,L,3D), fp16
__device__ float  g_x0[B * D * L];           // x0 gate, (B,D,L)
__device__ float  g_vx[B * D * L];           // v*x1, (B,D,L)
__device__ __half g_yt16[B * D * L];         // long-conv gated output (B,D,L), fp16
__device__ float  g_k [D * L];               // implicit filter (D,L)
__device__ float2 g_Kf[D * KFS];             // FFT of filter (half spectrum)
__device__ float  g_h [M_ROWS * D];          // out_proj + residual

__device__ __half g_xn16[M_ROWS * D];        // rmsnorm(x), fp16
__device__ __half g_g16 [M_ROWS * D];        // conv out, fp16
__device__ __half g_hn16[M_ROWS * D];        // rmsnorm(h), fp16
__device__ __half g_f1s [M_ROWS * 2 * D];    // ffn hidden, fp16

__device__ __half g_wiph[3 * D * D], g_wipl[3 * D * D];
__device__ __half g_woph[D * D],     g_wopl[D * D];
__device__ __half g_wf1h[2 * D * D];
__device__ __half g_wf2h[D * 2 * D];

// ---------------- helpers ----------------
__device__ __forceinline__ uint32_t smem_u32(const void* p) {
    uint32_t a;
    asm("{ .reg .u64 t; cvta.to.shared.u64 t, %1; cvt.u32.u64 %0, t; }" : "=r"(a) : "l"(p));
    return a;
}
__device__ __forceinline__ void cp_async16(uint32_t dst, const void* src) {
    asm volatile("cp.async.cg.shared.global [%0], [%1], 16;" :: "r"(dst), "l"(src));
}
#define CP_COMMIT() asm volatile("cp.async.commit_group;" ::: "memory")
template <int N_>
__device__ __forceinline__ void cp_wait() {
    asm volatile("cp.async.wait_group %0;" :: "n"(N_) : "memory");
}
__device__ __forceinline__ void mma_fp16(float* c, const uint32_t* a, const uint32_t* b) {
    asm volatile(
        "mma.sync.aligned.m16n8k16.row.col.f32.f16.f16.f32 "
        "{%0,%1,%2,%3}, {%4,%5,%6,%7}, {%8,%9}, {%0,%1,%2,%3};"
        : "+f"(c[0]), "+f"(c[1]), "+f"(c[2]), "+f"(c[3])
        : "r"(a[0]), "r"(a[1]), "r"(a[2]), "r"(a[3]), "r"(b[0]), "r"(b[1]));
}
__device__ __forceinline__ void ldsm_x4(uint32_t& r0, uint32_t& r1, uint32_t& r2, uint32_t& r3,
                                        uint32_t addr) {
    asm volatile("ldmatrix.sync.aligned.m8n8.x4.shared.b16 {%0,%1,%2,%3}, [%4];"
                 : "=r"(r0), "=r"(r1), "=r"(r2), "=r"(r3) : "r"(addr));
}
__device__ __forceinline__ float2 cmul(float2 a, float2 b) {
    return make_float2(a.x * b.x - a.y * b.y, a.x * b.y + a.y * b.x);
}

// ---------------- merged implicit filter: MLP + w3 proj + modulation -> k(D,L) ----------------
// grid (D/128, L/128), block 256. Each block recomputes h2 for its 128 l rows.
__global__ void filter_merged_kernel(const float* __restrict__ w1, const float* __restrict__ b1,
                                     const float* __restrict__ f1, const float* __restrict__ w2,
                                     const float* __restrict__ b2, const float* __restrict__ f2,
                                     const float* __restrict__ w3) {
    extern __shared__ float fs[];
    float* w2s = fs;                                 // [64][65]
    float (*sh2)[65] = (float(*)[65])(fs + 64 * 65); // [128][65]  h2 tile
    float (*sw3)[65] = (float(*)[65])(fs + 64 * 65 + 128 * 65); // [128][65] h1 staging, then w3
    const int d0 = blockIdx.x * 128;
    const int l0 = blockIdx.y * 128;
    const int tid = threadIdx.x;

    // load w2 into smem (padded rows)
    for (int i = tid; i < 64 * 64; i += 256) {
        w2s[(i >> 6) * 65 + (i & 63)] = w2[i];
    }
    // h1 into sw3 staging
    for (int idx = tid; idx < 128 * 64; idx += 256) {
        const int ll = idx >> 6;
        const int r = idx & 63;
        const int l = l0 + ll;
        const float t = (float)l * (1.0f / (L - 1));
        const float ang = 1e-4f * 6.283185307179586f * (float)l / (float)L;
        const float a = t * w1[r * 3 + 0] + cosf(ang) * w1[r * 3 + 1]
                      - sinf(ang) * w1[r * 3 + 2] + b1[r];
        sw3[ll][r] = sinf(f1[r] * a);
    }
    __syncthreads();
    // h2 into sh2
    for (int idx = tid; idx < 128 * 64; idx += 256) {
        const int ll = idx >> 6;
        const int r = idx & 63;
        float acc = b2[r];
        #pragma unroll
        for (int k = 0; k < 64; k++) acc += w2s[r * 65 + k] * sw3[ll][k];
        sh2[ll][r] = sinf(f2[r] * acc);
    }
    __syncthreads();
    // load w3 tile (overwrite staging)
    for (int i = tid; i < 128 * 16; i += 256) {
        const int row = i >> 4;
        const int c4 = (i & 15) * 4;
        const float4 v = *(const float4*)&w3[(size_t)(d0 + row) * 64 + c4];
        sw3[row][c4] = v.x; sw3[row][c4 + 1] = v.y; sw3[row][c4 + 2] = v.z; sw3[row][c4 + 3] = v.w;
    }
    __syncthreads();

    const int tx = tid & 15;
    const int ty = tid >> 4;
    float acc[8][8];
    #pragma unroll
    for (int i = 0; i < 8; i++)
        #pragma unroll
        for (int j = 0; j < 8; j++) acc[i][j] = 0.f;
    #pragma unroll 16
    for (int r = 0; r < 64; r++) {
        float av[8], bv[8];
        #pragma unroll
        for (int i = 0; i < 8; i++) av[i] = sw3[ty * 8 + i][r];
        #pragma unroll
        for (int j = 0; j < 8; j++) bv[j] = sh2[tx * 8 + j][r];
        #pragma unroll
        for (int i = 0; i < 8; i++)
            #pragma unroll
            for (int j = 0; j < 8; j++) acc[i][j] += av[i] * bv[j];
    }
    const float min_d = -3.0701134573253940f;
    const float max_d = -15.350567286626971f;
    #pragma unroll
    for (int i = 0; i < 8; i++) {
        const int d = d0 + ty * 8 + i;
        const float delta = fabsf(min_d + (max_d - min_d) * (float)d * (1.0f / (D - 1)));
        #pragma unroll
        for (int j = 0; j < 8; j++) {
            const int l = l0 + tx * 8 + j;
            const float t = (float)l * (1.0f / (L - 1));
            g_k[(size_t)d * L + l] = acc[i][j] * expf(-t * delta);
        }
    }
}

// ---------------- 4096-pt radix-4 Stockham FFT (6 fused passes) ----------------
__device__ __forceinline__ float2* fft4096_r4(float2* buf0, float2* buf1, const float2* tw,
                                              int tid, int T) {
    float2* src = buf0;
    float2* dst = buf1;
    int ls = 0;
    #pragma unroll
    for (int pass = 0; pass < 6; pass++) {
        const int s = 1 << ls;
        for (int x = tid; x < NFFT / 4; x += T) {
            const int ps = x & ~(s - 1);
            const float2 w1 = tw[ps];
            const float2 w2 = tw[2 * ps];
            float2 a = src[x];
            float2 b = src[x + 2048];
            float2 c = src[x + 1024];
            float2 d = src[x + 3072];
            float2 u0 = make_float2(a.x + b.x, a.y + b.y);
            float2 t1 = make_float2(a.x - b.x, a.y - b.y);
            float2 u1 = cmul(t1, w1);
            float2 v0 = make_float2(c.x + d.x, c.y + d.y);
            float2 t2 = make_float2(c.x - d.x, c.y - d.y);
            float2 t2w = cmul(t2, w1);
            float2 v1 = make_float2(t2w.y, -t2w.x);
            const int base = x + 3 * ps;
            dst[base]         = make_float2(u0.x + v0.x, u0.y + v0.y);
            dst[base + 2 * s] = cmul(make_float2(u0.x - v0.x, u0.y - v0.y), w2);
            dst[base + s]     = make_float2(u1.x + v1.x, u1.y + v1.y);
            dst[base + 3 * s] = cmul(make_float2(u1.x - v1.x, u1.y - v1.y), w2);
        }
        __syncthreads();
        float2* tp = src; src = dst; dst = tp;
        ls += 2;
    }
    return src;
}

__device__ __forceinline__ void build_tw(float2* tw, int tid, int T) {
    for (int j = tid; j < NFFT / 2; j += T) {
        float a = -6.283185307179586f * (float)j * (1.0f / NFFT);
        float sn, cs;
        sincosf(a, &sn, &cs);
        tw[j] = make_float2(cs, sn);
    }
}

__global__ void kf_kernel() {
    extern __shared__ float2 shf[];
    float2* A = shf;
    float2* Btmp = shf + NFFT;
    float2* tw = shf + 2 * NFFT;
    const int d = blockIdx.x;
    const int tid = threadIdx.x;
    const int T = blockDim.x;
    build_tw(tw, tid, T);
    const float* kr = g_k + (size_t)d * L;
    for (int i = tid; i < L; i += T) {
        A[i]     = make_float2(kr[i], 0.f);
        A[i + L] = make_float2(0.f, 0.f);
    }
    __syncthreads();
    float2* R = fft4096_r4(A, Btmp, tw, tid, T);
    for (int i = tid; i <= NFFT / 2; i += T) g_Kf[(size_t)d * KFS + i] = R[i];
}

// ---------------- rmsnorm -> single fp16 ----------------
__global__ void rmsnorm_h_kernel(const float* __restrict__ x, const float* __restrict__ w,
                                 __half* __restrict__ oh) {
    const int row = blockIdx.x;
    const int tid = threadIdx.x;
    const int lane = tid & 31;
    const int wrp = tid >> 5;
    const float4* xr = (const float4*)(x + (size_t)row * D);
    float4 v = xr[tid];
    float s = v.x * v.x + v.y * v.y + v.z * v.z + v.w * v.w;
    #pragma unroll
    for (int off = 16; off > 0; off >>= 1) s += __shfl_xor_sync(0xFFFFFFFF, s, off);
    __shared__ float red[8];
    if (lane == 0) red[wrp] = s;
    __syncthreads();
    if (wrp == 0) {
        float r = (lane < 8) ? red[lane] : 0.f;
        #pragma unroll
        for (int off = 4; off > 0; off >>= 1) r += __shfl_xor_sync(0xFFFFFFFF, r, off);
        if (lane == 0) red[0] = r;
    }
    __syncthreads();
    float scale = rsqrtf(red[0] * (1.0f / D) + 1e-8f);
    float4 wv = ((const float4*)w)[tid];
    ((__half2*)(oh + (size_t)row * D))[tid * 2 + 0] =
        __floats2half2_rn(v.x * scale * wv.x, v.y * scale * wv.y);
    ((__half2*)(oh + (size_t)row * D))[tid * 2 + 1] =
        __floats2half2_rn(v.z * scale * wv.z, v.w * scale * wv.w);
}

// ---------------- weight split fp32 -> fp16 hi/lo ----------------
__global__ void wsplit_h_kernel(const float* __restrict__ w, __half* __restrict__ wh,
                                __half* __restrict__ wl, int n4) {
    int i = blockIdx.x * 256 + threadIdx.x;
    if (i < n4) {
        float4 v = ((const float4*)w)[i];
        __half hx = __float2half_rn(v.x), hy = __float2half_rn(v.y);
        __half hz = __float2half_rn(v.z), hw = __float2half_rn(v.w);
        ((__half2*)wh)[i * 2 + 0] = __halves2half2(hx, hy);
        ((__half2*)wh)[i * 2 + 1] = __halves2half2(hz, hw);
        ((__half2*)wl)[i * 2 + 0] = __halves2half2(__float2half_rn(v.x - __half2float(hx)),
                                                   __float2half_rn(v.y - __half2float(hy)));
        ((__half2*)wl)[i * 2 + 1] = __halves2half2(__float2half_rn(v.z - __half2float(hz)),
                                                   __float2half_rn(v.w - __half2float(hw)));
    }
}

// ---------------- weight convert fp32 -> single fp16 ----------------
__global__ void wconv_h_kernel(const float* __restrict__ w, __half* __restrict__ wh, int n4) {
    int i = blockIdx.x * 256 + threadIdx.x;
    if (i < n4) {
        float4 v = ((const float4*)w)[i];
        ((__half2*)wh)[i * 2 + 0] = __floats2half2_rn(v.x, v.y);
        ((__half2*)wh)[i * 2 + 1] = __floats2half2_rn(v.z, v.w);
    }
}

__device__ __forceinline__ float gelu_tanh(float x) {
    float c = 0.7978845608028654f * (x + 0.044715f * x * x * x);
    return 0.5f * x * (1.0f + tanhf(c));
}

#define BK 32
#define SROW 80
#define TILE_A_B (128 * SROW)         // 10240
#define TILE_W_B (64 * SROW)          // 5120
#define STAGE_B2 (TILE_A_B + 2 * TILE_W_B)   // 20480
#define STAGE_B1 (TILE_A_B + TILE_W_B)       // 15360
#define NSTAGE 3

// ---------------- fp16 2-term GEMM, CTA 128x64: C = A @ (Wh+Wl)^T ----------------
// EPI: 1 = +bias+res -> fp32 ; 3 = +bias -> fp16
template <int EPI>
__global__ void __launch_bounds__(256, 3)
tgemm_h2_kernel(const __half* __restrict__ Ap,
                const __half* __restrict__ Whp, const __half* __restrict__ Wlp,
                const float* __restrict__ bias, const float* __restrict__ res,
                float* __restrict__ Cf, __half* __restrict__ Chs, int N, int K) {
    extern __shared__ char smem[];
    const uint32_t sbase = smem_u32(smem);

    const int tid = threadIdx.x;
    const int wid = tid >> 5;
    const int lane = tid & 31;
    const int wm = wid & 1;
    const int wn = wid >> 1;
    const int g = lane >> 2;
    const int t = lane & 3;
    const int bm = blockIdx.y * 128;
    const int bn = blockIdx.x * 64;
    const int NC = K / BK;

    const uint32_t a_off = (uint32_t)(wm * 64 + (lane & 15)) * SROW + ((lane & 16) ? 16u : 0u);
    const uint32_t b_off = (uint32_t)(wn * 16 + ((lane >> 4) << 3) + (lane & 7)) * SROW
                         + (((lane >> 3) & 1) ? 16u : 0u);

    auto load_chunk = [&](int ck, int st) {
        const int k0 = ck * BK;
        const uint32_t stage = sbase + st * STAGE_B2;
        #pragma unroll
        for (int j = 0; j < 4; j++) {
            const int idx = j * 256 + tid;
            const int r = idx >> 2;
            const int ch = idx & 3;
            const __half* src;
            uint32_t dst;
            if (r < 128) {
                src = Ap + (size_t)(bm + r) * K + k0 + ch * 8;
                dst = stage + r * SROW + ch * 16;
            } else if (r < 192) {
                src = Whp + (size_t)(bn + r - 128) * K + k0 + ch * 8;
                dst = stage + TILE_A_B + (r - 128) * SROW + ch * 16;
            } else {
                src = Wlp + (size_t)(bn + r - 192) * K + k0 + ch * 8;
                dst = stage + TILE_A_B + TILE_W_B + (r - 192) * SROW + ch * 16;
            }
            cp_async16(dst, src);
        }
        CP_COMMIT();
    };

    float acc[4][2][4];
    #pragma unroll
    for (int mi = 0; mi < 4; mi++)
        #pragma unroll
        for (int ni = 0; ni < 2; ni++)
            #pragma unroll
            for (int q = 0; q < 4; q++) acc[mi][ni][q] = 0.f;

    load_chunk(0, 0);
    load_chunk(1, 1);

    int st = 0;
    for (int ck = 0; ck < NC; ck++) {
        cp_wait<1>();
        __syncthreads();
        if (ck + 2 < NC) load_chunk(ck + 2, (st + 2) % NSTAGE);

        const uint32_t stage = sbase + st * STAGE_B2;
        const uint32_t sA  = stage + a_off;
        const uint32_t sWh = stage + TILE_A_B + b_off;
        const uint32_t sWl = stage + TILE_A_B + TILE_W_B + b_off;

        #pragma unroll
        for (int ks = 0; ks < 2; ks++) {
            const uint32_t kb = ks * 32;

            uint32_t bh[2][2], bl[2][2];
            ldsm_x4(bh[0][0], bh[0][1], bh[1][0], bh[1][1], sWh + kb);
            ldsm_x4(bl[0][0], bl[0][1], bl[1][0], bl[1][1], sWl + kb);

            uint32_t af[4][4];
            #pragma unroll
            for (int mi = 0; mi < 4; mi++)
                ldsm_x4(af[mi][0], af[mi][1], af[mi][2], af[mi][3],
                        sA + (uint32_t)(mi * 16) * SROW + kb);
            #pragma unroll
            for (int mi = 0; mi < 4; mi++)
                #pragma unroll
                for (int ni = 0; ni < 2; ni++) mma_fp16(acc[mi][ni], af[mi], bh[ni]);
            #pragma unroll
            for (int mi = 0; mi < 4; mi++)
                #pragma unroll
                for (int ni = 0; ni < 2; ni++) mma_fp16(acc[mi][ni], af[mi], bl[ni]);
        }
        st = (st + 1) % NSTAGE;
    }

    #pragma unroll
    for (int mi = 0; mi < 4; mi++) {
        const int row0 = bm + wm * 64 + mi * 16 + g;
        #pragma unroll
        for (int ni = 0; ni < 2; ni++) {
            const int col = bn + wn * 16 + ni * 8 + 2 * t;
            const float b0 = __ldg(&bias[col]);
            const float b1 = __ldg(&bias[col + 1]);
            float v0 = acc[mi][ni][0] + b0;
            float v1 = acc[mi][ni][1] + b1;
            float v2 = acc[mi][ni][2] + b0;
            float v3 = acc[mi][ni][3] + b1;
            if (EPI == 1) {
                const float2 r0 = *(const float2*)&res[(size_t)row0 * N + col];
                const float2 r1 = *(const float2*)&res[(size_t)(row0 + 8) * N + col];
                *(float2*)&Cf[(size_t)row0 * N + col] = make_float2(v0 + r0.x, v1 + r0.y);
                *(float2*)&Cf[(size_t)(row0 + 8) * N + col] = make_float2(v2 + r1.x, v3 + r1.y);
            } else {
                *(__half2*)&Chs[(size_t)row0 * N + col] = __floats2half2_rn(v0, v1);
                *(__half2*)&Chs[(size_t)(row0 + 8) * N + col] = __floats2half2_rn(v2, v3);
            }
        }
    }
}

// ---------------- fp16 1-term GEMM, CTA 128x64: C = A @ Wh^T ----------------
// EPI: 1 = +bias+res -> fp32 ; 2 = gelu(+bias) -> fp16
template <int EPI>
__global__ void __launch_bounds__(256, 3)
tgemm_h1_kernel(const __half* __restrict__ Ap, const __half* __restrict__ Whp,
                const float* __restrict__ bias, const float* __restrict__ res,
                float* __restrict__ Cf, __half* __restrict__ Chs, int N, int K) {
    extern __shared__ char smem[];
    const uint32_t sbase = smem_u32(smem);

    const int tid = threadIdx.x;
    const int wid = tid >> 5;
    const int lane = tid & 31;
    const int wm = wid & 1;
    const int wn = wid >> 1;
    const int g = lane >> 2;
    const int t = lane & 3;
    const int bm = blockIdx.y * 128;
    const int bn = blockIdx.x * 64;
    const int NC = K / BK;

    const uint32_t a_off = (uint32_t)(wm * 64 + (lane & 15)) * SROW + ((lane & 16) ? 16u : 0u);
    const uint32_t b_off = (uint32_t)(wn * 16 + ((lane >> 4) << 3) + (lane & 7)) * SROW
                         + (((lane >> 3) & 1) ? 16u : 0u);

    auto load_chunk = [&](int ck, int st) {
        const int k0 = ck * BK;
        const uint32_t stage = sbase + st * STAGE_B1;
        #pragma unroll
        for (int j = 0; j < 3; j++) {
            const int idx = j * 256 + tid;
            const int r = idx >> 2;
            const int ch = idx & 3;
            const __half* src;
            uint32_t dst;
            if (r < 128) {
                src = Ap + (size_t)(bm + r) * K + k0 + ch * 8;
                dst = stage + r * SROW + ch * 16;
            } else {
                src = Whp + (size_t)(bn + r - 128) * K + k0 + ch * 8;
                dst = stage + TILE_A_B + (r - 128) * SROW + ch * 16;
            }
            cp_async16(dst, src);
        }
        CP_COMMIT();
    };

    float acc[4][2][4];
    #pragma unroll
    for (int mi = 0; mi < 4; mi++)
        #pragma unroll
        for (int ni = 0; ni < 2; ni++)
            #pragma unroll
            for (int q = 0; q < 4; q++) acc[mi][ni][q] = 0.f;

    load_chunk(0, 0);
    load_chunk(1, 1);

    int st = 0;
    for (int ck = 0; ck < NC; ck++) {
        cp_wait<1>();
        __syncthreads();
        if (ck + 2 < NC) load_chunk(ck + 2, (st + 2) % NSTAGE);

        const uint32_t stage = sbase + st * STAGE_B1;
        const uint32_t sA  = stage + a_off;
        const uint32_t sWh = stage + TILE_A_B + b_off;

        #pragma unroll
        for (int ks = 0; ks < 2; ks++) {
            const uint32_t kb = ks * 32;

            uint32_t bh[2][2];
            ldsm_x4(bh[0][0], bh[0][1], bh[1][0], bh[1][1], sWh + kb);

            uint32_t af[4][4];
            #pragma unroll
            for (int mi = 0; mi < 4; mi++)
                ldsm_x4(af[mi][0], af[mi][1], af[mi][2], af[mi][3],
                        sA + (uint32_t)(mi * 16) * SROW + kb);
            #pragma unroll
            for (int mi = 0; mi < 4; mi++)
                #pragma unroll
                for (int ni = 0; ni < 2; ni++) mma_fp16(acc[mi][ni], af[mi], bh[ni]);
        }
        st = (st + 1) % NSTAGE;
    }

    #pragma unroll
    for (int mi = 0; mi < 4; mi++) {
        const int row0 = bm + wm * 64 + mi * 16 + g;
        #pragma unroll
        for (int ni = 0; ni < 2; ni++) {
            const int col = bn + wn * 16 + ni * 8 + 2 * t;
            const float b0 = __ldg(&bias[col]);
            const float b1 = __ldg(&bias[col + 1]);
            float v0 = acc[mi][ni][0] + b0;
            float v1 = acc[mi][ni][1] + b1;
            float v2 = acc[mi][ni][2] + b0;
            float v3 = acc[mi][ni][3] + b1;
            if (EPI == 1) {
                const float2 r0 = *(const float2*)&res[(size_t)row0 * N + col];
                const float2 r1 = *(const float2*)&res[(size_t)(row0 + 8) * N + col];
                *(float2*)&Cf[(size_t)row0 * N + col] = make_float2(v0 + r0.x, v1 + r0.y);
                *(float2*)&Cf[(size_t)(row0 + 8) * N + col] = make_float2(v2 + r1.x, v3 + r1.y);
            } else {
                *(__half2*)&Chs[(size_t)row0 * N + col] =
                    __floats2half2_rn(gelu_tanh(v0), gelu_tanh(v1));
                *(__half2*)&Chs[(size_t)(row0 + 8) * N + col] =
                    __floats2half2_rn(gelu_tanh(v2), gelu_tanh(v3));
            }
        }
    }
}

// ---------------- short depthwise causal conv (k=3) + gate prep (fp16 input) ----------------
__global__ void shortfilter_kernel(const __half* __restrict__ u, const float* __restrict__ sw,
                                   const float* __restrict__ sb) {
    __shared__ float su[3][34][33];
    __shared__ float st0[32][33];
    __shared__ float st1[32][33];
    const int b  = blockIdx.z;
    const int d0 = blockIdx.y * 32;
    const int l0 = blockIdx.x * 32;
    const int tx = threadIdx.x;
    const int ty = threadIdx.y;
    const __half* ub = u + (size_t)b * L * 3 * D;

    #pragma unroll
    for (int grp = 0; grp < 3; grp++) {
        int c = grp * D + d0 + tx;
        {
            int l = l0 - 2 + ty;
            su[grp][ty][tx] = (l >= 0) ? __half2float(ub[(size_t)l * 3 * D + c]) : 0.f;
        }
        if (ty < 2) {
            int r = 32 + ty;
            int l = l0 - 2 + r;
            su[grp][r][tx] = __half2float(ub[(size_t)l * 3 * D + c]);
        }
    }
    __syncthreads();

    float a[3];
    #pragma unroll
    for (int grp = 0; grp < 3; grp++) {
        int c = grp * D + d0 + tx;
        float w0 = sw[c * 3 + 0], w1 = sw[c * 3 + 1], w2 = sw[c * 3 + 2];
        a[grp] = w0 * su[grp][ty][tx] + w1 * su[grp][ty + 1][tx] + w2 * su[grp][ty + 2][tx] + sb[c];
    }
    st0[ty][tx] = a[0];
    st1[ty][tx] = a[2] * a[1];
    __syncthreads();

    size_t o = ((size_t)b * D + (d0 + ty)) * L + l0 + tx;
    g_x0[o] = st0[tx][ty];
    g_vx[o] = st1[tx][ty];
}

// ---------------- fused FFT conv: 2 real channels packed per complex FFT ----------------
__global__ void conv_gate2_kernel(const float* __restrict__ fbias) {
    extern __shared__ float2 shf[];
    float2* A = shf;
    float2* Btmp = shf + NFFT;
    float2* tw = shf + 2 * NFFT;
    const int bp = blockIdx.x;
    const int pair = bp & (D / 2 - 1);
    const int b = bp / (D / 2);
    const int d0 = pair * 2;
    const int d1 = d0 + 1;
    const int tid = threadIdx.x;
    const int T = blockDim.x;

    build_tw(tw, tid, T);
    const float* v0 = g_vx + ((size_t)b * D + d0) * L;
    const float* v1 = g_vx + ((size_t)b * D + d1) * L;
    for (int i = tid; i < L; i += T) {
        A[i]     = make_float2(v0[i], v1[i]);
        A[i + L] = make_float2(0.f, 0.f);
    }
    __syncthreads();
    float2* R = fft4096_r4(A, Btmp, tw, tid, T);

    const float2* kf0 = g_Kf + (size_t)d0 * KFS;
    const float2* kf1 = g_Kf + (size_t)d1 * KFS;
    const float inv = 1.0f / NFFT;
    const int half = NFFT / 2;
    for (int k = tid; k <= half; k += T) {
        const int km = (NFFT - k) & (NFFT - 1);
        const float2 z1 = R[k];
        const float2 z2 = R[km];
        const float v1r = 0.5f * (z1.x + z2.x), v1i = 0.5f * (z1.y - z2.y);
        const float dr  = 0.5f * (z1.x - z2.x), di  = 0.5f * (z1.y + z2.y);
        const float v2r = di, v2i = -dr;
        const float2 k1 = kf0[k], k2 = kf1[k];
        const float y1r = (v1r * k1.x - v1i * k1.y) * inv;
        const float y1i = (v1r * k1.y + v1i * k1.x) * inv;
        const float y2r = (v2r * k2.x - v2i * k2.y) * inv;
        const float y2i = (v2r * k2.y + v2i * k2.x) * inv;
        R[k]  = make_float2(y1r - y2i, -(y1i + y2r));
        if (km != k) R[km] = make_float2(y1r + y2i, y1i - y2r);
    }
    __syncthreads();
    float2* other = (R == A) ? Btmp : A;
    float2* R2 = fft4096_r4(R, other, tw, tid, T);

    const float b0 = fbias[d0];
    const float b1 = fbias[d1];
    const float* x00 = g_x0 + ((size_t)b * D + d0) * L;
    const float* x01 = g_x0 + ((size_t)b * D + d1) * L;
    __half* y0 = g_yt16 + ((size_t)b * D + d0) * L;
    __half* y1 = g_yt16 + ((size_t)b * D + d1) * L;
    for (int i = tid; i < L; i += T) {
        y0[i] = __float2half_rn((R2[i].x + v0[i] * b0) * x00[i]);
        y1[i] = __float2half_rn((-R2[i].y + v1[i] * b1) * x01[i]);
    }
}

// ---------------- transpose (B,D,L) fp16 -> (B,L,D) fp16 ----------------
__global__ void transconv_kernel() {
    __shared__ __half t[32][34];
    const int l0 = blockIdx.x * 32;
    const int d0 = blockIdx.y * 32;
    const int b  = blockIdx.z;
    const int tx = threadIdx.x;
    const int ty = threadIdx.y;   // 0..7
    #pragma unroll
    for (int i = 0; i < 4; i++)
        t[ty + i * 8][tx] = g_yt16[((size_t)b * D + d0 + ty + i * 8) * L + l0 + tx];
    __syncthreads();
    #pragma unroll
    for (int i = 0; i < 4; i++) {
        int l = l0 + ty + i * 8;
        int d = d0 + tx;
        g_g16[((size_t)b * L + l) * D + d] = t[tx][ty + i * 8];
    }
}

// ---------------- launch ----------------
extern "C" void kernel_launch(void* const* d_in, const int* in_sizes, int n_in,
                              void* d_out, int out_size) {
    const float* x    = (const float*)d_in[0];
    const float* nin  = (const float*)d_in[1];
    const float* ipw  = (const float*)d_in[2];
    const float* ipb  = (const float*)d_in[3];
    const float* sfw  = (const float*)d_in[4];
    const float* sfb  = (const float*)d_in[5];
    const float* w1   = (const float*)d_in[6];
    const float* b1   = (const float*)d_in[7];
    const float* f1   = (const float*)d_in[8];
    const float* w2   = (const float*)d_in[9];
    const float* b2   = (const float*)d_in[10];
    const float* f2   = (const float*)d_in[11];
    const float* w3   = (const float*)d_in[12];
    const float* fbias= (const float*)d_in[13];
    const float* opw  = (const float*)d_in[14];
    const float* opb  = (const float*)d_in[15];
    const float* nw   = (const float*)d_in[16];
    const float* fw1  = (const float*)d_in[17];
    const float* fb1  = (const float*)d_in[18];
    const float* fw2  = (const float*)d_in[19];
    const float* fb2  = (const float*)d_in[20];
    float* out = (float*)d_out;

    const int fft_smem = NFFT * 2 * sizeof(float2) + (NFFT / 2) * sizeof(float2);  // 80 KB
    const int gemm2_smem = NSTAGE * STAGE_B2;    // 61440
    const int gemm1_smem = NSTAGE * STAGE_B1;    // 46080
    const int fmerged_smem = (64 * 65 + 2 * 128 * 65) * sizeof(float);  // 83200
    cudaFuncSetAttribute(kf_kernel, cudaFuncAttributeMaxDynamicSharedMemorySize, fft_smem);
    cudaFuncSetAttribute(conv_gate2_kernel, cudaFuncAttributeMaxDynamicSharedMemorySize, fft_smem);
    cudaFuncSetAttribute(tgemm_h2_kernel<1>, cudaFuncAttributeMaxDynamicSharedMemorySize, gemm2_smem);
    cudaFuncSetAttribute(tgemm_h2_kernel<3>, cudaFuncAttributeMaxDynamicSharedMemorySize, gemm2_smem);
    cudaFuncSetAttribute(tgemm_h1_kernel<1>, cudaFuncAttributeMaxDynamicSharedMemorySize, gemm1_smem);
    cudaFuncSetAttribute(tgemm_h1_kernel<2>, cudaFuncAttributeMaxDynamicSharedMemorySize, gemm1_smem);
    cudaFuncSetAttribute(filter_merged_kernel, cudaFuncAttributeMaxDynamicSharedMemorySize, fmerged_smem);

    float *h;
    __half *u16, *xn16, *g16, *hn16, *f1s;
    __half *wiph, *wipl, *woph, *wopl, *wf1h, *wf2h;
    cudaGetSymbolAddress((void**)&u16, g_u16);
    cudaGetSymbolAddress((void**)&h, g_h);
    cudaGetSymbolAddress((void**)&xn16, g_xn16);
    cudaGetSymbolAddress((void**)&g16, g_g16);
    cudaGetSymbolAddress((void**)&hn16, g_hn16);
    cudaGetSymbolAddress((void**)&f1s, g_f1s);
    cudaGetSymbolAddress((void**)&wiph, g_wiph); cudaGetSymbolAddress((void**)&wipl, g_wipl);
    cudaGetSymbolAddress((void**)&woph, g_woph); cudaGetSymbolAddress((void**)&wopl, g_wopl);
    cudaGetSymbolAddress((void**)&wf1h, g_wf1h);
    cudaGetSymbolAddress((void**)&wf2h, g_wf2h);

    // launch 0-2: prep; launch 3: kf_kernel (ncu profiles index 3 -> FFT path data)
    wsplit_h_kernel<<<(3 * D * D / 4 + 255) / 256, 256>>>(ipw, wiph, wipl, 3 * D * D / 4);
    rmsnorm_h_kernel<<<M_ROWS, 256>>>(x, nin, xn16);
    filter_merged_kernel<<<dim3(D / 128, L / 128), 256, fmerged_smem>>>(
        w1, b1, f1, w2, b2, f2, w3);
    kf_kernel<<<D, 512, fft_smem>>>();

    // in_proj (fp16x2)
    tgemm_h2_kernel<3><<<dim3(3 * D / 64, M_ROWS / 128), 256, gemm2_smem>>>(
        xn16, wiph, wipl, ipb, nullptr, nullptr, u16, 3 * D, D);

    // short filter + gating split
    shortfilter_kernel<<<dim3(L / 32, D / 32, B), dim3(32, 32)>>>(u16, sfw, sfb);

    // long conv via packed FFT + gate, then transpose
    conv_gate2_kernel<<<B * D / 2, 512, fft_smem>>>(fbias);
    transconv_kernel<<<dim3(L / 32, D / 32, B), dim3(32, 8)>>>();

    // out_proj + residual (fp16x2)
    wsplit_h_kernel<<<(D * D / 4 + 255) / 256, 256>>>(opw, woph, wopl, D * D / 4);
    tgemm_h2_kernel<1><<<dim3(D / 64, M_ROWS / 128), 256, gemm2_smem>>>(
        g16, woph, wopl, opb, x, h, nullptr, D, D);

    // FFN (fp16 1-term)
    rmsnorm_h_kernel<<<M_ROWS, 256>>>(h, nw, hn16);
    wconv_h_kernel<<<(2 * D * D / 4 + 255) / 256, 256>>>(fw1, wf1h, 2 * D * D / 4);
    tgemm_h1_kernel<2><<<dim3(2 * D / 64, M_ROWS / 128), 256, gemm1_smem>>>(
        hn16, wf1h, fb1, nullptr, nullptr, f1s, 2 * D, D);
    wconv_h_kernel<<<(D * 2 * D / 4 + 255) / 256, 256>>>(fw2, wf2h, D * 2 * D / 4);
    tgemm_h1_kernel<1><<<dim3(D / 64, M_ROWS / 128), 256, gemm1_smem>>>(
        f1s, wf2h, fb2, h, out, nullptr, D, 2 * D);
}

// round 17
// speedup vs baseline: 1.5137x; 1.5137x over previous
#include <cuda_runtime.h>
#include <cuda_bf16.h>
#include <cuda_fp16.h>
#include <math.h>
#include <stdint.h>

#define B 4
#define L 2048
#define D 1024
#define M_ROWS (B * L)          // 8192
#define NFFT 4096

// ---------------- scratch (static __device__, no allocation) ----------------
__device__ __half g_u16[M_ROWS * 3 * D];     // in_proj output (B,L,3D), fp16
__device__ float  g_x0[B * D * L];           // x0 gate, (B,D,L)
__device__ float  g_vx[B * D * L];           // v*x1, (B,D,L)
__device__ float  g_yt[B * D * L];           // long-conv gated output (B,D,L)
__device__ float  g_h2a[L * 64];             // filter MLP hidden h2
__device__ float  g_k [D * L];               // implicit filter (D,L)
__device__ float2 g_Kf[D * NFFT];            // FFT of filter
__device__ float  g_h [M_ROWS * D];          // out_proj + residual

__device__ __half g_xn16[M_ROWS * D];        // rmsnorm(x), fp16
__device__ __half g_g16 [M_ROWS * D];        // conv out, fp16
__device__ __half g_hn16[M_ROWS * D];        // rmsnorm(h), fp16
__device__ __half g_f1s [M_ROWS * 2 * D];    // ffn hidden, fp16

__device__ __half g_wiph[3 * D * D], g_wipl[3 * D * D];
__device__ __half g_woph[D * D],     g_wopl[D * D];
__device__ __half g_wf1h[2 * D * D];                      // ffn1 W, single fp16
__device__ __half g_wf2h[D * 2 * D];                      // ffn2 W, single fp16

// ---------------- helpers ----------------
__device__ __forceinline__ uint32_t smem_u32(const void* p) {
    uint32_t a;
    asm("{ .reg .u64 t; cvta.to.shared.u64 t, %1; cvt.u32.u64 %0, t; }" : "=r"(a) : "l"(p));
    return a;
}
__device__ __forceinline__ void cp_async16(uint32_t dst, const void* src) {
    asm volatile("cp.async.cg.shared.global [%0], [%1], 16;" :: "r"(dst), "l"(src));
}
#define CP_COMMIT() asm volatile("cp.async.commit_group;" ::: "memory")
template <int N_>
__device__ __forceinline__ void cp_wait() {
    asm volatile("cp.async.wait_group %0;" :: "n"(N_) : "memory");
}
__device__ __forceinline__ void mma_fp16(float* c, const uint32_t* a, const uint32_t* b) {
    asm volatile(
        "mma.sync.aligned.m16n8k16.row.col.f32.f16.f16.f32 "
        "{%0,%1,%2,%3}, {%4,%5,%6,%7}, {%8,%9}, {%0,%1,%2,%3};"
        : "+f"(c[0]), "+f"(c[1]), "+f"(c[2]), "+f"(c[3])
        : "r"(a[0]), "r"(a[1]), "r"(a[2]), "r"(a[3]), "r"(b[0]), "r"(b[1]));
}
__device__ __forceinline__ void ldsm_x4(uint32_t& r0, uint32_t& r1, uint32_t& r2, uint32_t& r3,
                                        uint32_t addr) {
    asm volatile("ldmatrix.sync.aligned.m8n8.x4.shared.b16 {%0,%1,%2,%3}, [%4];"
                 : "=r"(r0), "=r"(r1), "=r"(r2), "=r"(r3) : "r"(addr));
}
__device__ __forceinline__ float2 cmul(float2 a, float2 b) {
    return make_float2(a.x * b.x - a.y * b.y, a.x * b.y + a.y * b.x);
}

// ---------------- implicit filter: stages 1-2 -> h2[L,64] ----------------
__global__ void filter_h2_kernel(const float* __restrict__ w1, const float* __restrict__ b1,
                                 const float* __restrict__ f1, const float* __restrict__ w2,
                                 const float* __restrict__ b2, const float* __restrict__ f2) {
    const int l = blockIdx.x;
    const int r = threadIdx.x;   // 64 threads
    __shared__ float h1[64];
    const float t  = (float)l * (1.0f / (L - 1));
    const float ang = 1e-4f * 6.283185307179586f * (float)l / (float)L;
    const float z0 = t, z1 = cosf(ang), z2 = -sinf(ang);
    float a = z0 * w1[r * 3 + 0] + z1 * w1[r * 3 + 1] + z2 * w1[r * 3 + 2] + b1[r];
    h1[r] = sinf(f1[r] * a);
    __syncthreads();
    float acc = b2[r];
    #pragma unroll
    for (int k = 0; k < 64; k++) acc += w2[r * 64 + k] * h1[k];
    g_h2a[l * 64 + r] = sinf(f2[r] * acc);
}

// ---------------- implicit filter: w3 projection + modulation -> k(D,L) ----------------
__global__ void filter_proj_kernel(const float* __restrict__ w3) {
    extern __shared__ float fs[];
    float (*sh2)[65] = (float(*)[65])fs;
    float (*sw3)[65] = (float(*)[65])(fs + 128 * 65);
    const int d0 = blockIdx.x * 128;
    const int l0 = blockIdx.y * 128;
    const int tid = threadIdx.x;
    for (int i = tid; i < 128 * 16; i += 256) {
        const int row = i >> 4;
        const int c4 = (i & 15) * 4;
        const float4 v = *(const float4*)&g_h2a[(l0 + row) * 64 + c4];
        sh2[row][c4] = v.x; sh2[row][c4 + 1] = v.y; sh2[row][c4 + 2] = v.z; sh2[row][c4 + 3] = v.w;
    }
    for (int i = tid; i < 128 * 16; i += 256) {
        const int row = i >> 4;
        const int c4 = (i & 15) * 4;
        const float4 v = *(const float4*)&w3[(size_t)(d0 + row) * 64 + c4];
        sw3[row][c4] = v.x; sw3[row][c4 + 1] = v.y; sw3[row][c4 + 2] = v.z; sw3[row][c4 + 3] = v.w;
    }
    __syncthreads();

    const int tx = tid & 15;
    const int ty = tid >> 4;
    float acc[8][8];
    #pragma unroll
    for (int i = 0; i < 8; i++)
        #pragma unroll
        for (int j = 0; j < 8; j++) acc[i][j] = 0.f;
    #pragma unroll 16
    for (int r = 0; r < 64; r++) {
        float av[8], bv[8];
        #pragma unroll
        for (int i = 0; i < 8; i++) av[i] = sw3[ty * 8 + i][r];
        #pragma unroll
        for (int j = 0; j < 8; j++) bv[j] = sh2[tx * 8 + j][r];
        #pragma unroll
        for (int i = 0; i < 8; i++)
            #pragma unroll
            for (int j = 0; j < 8; j++) acc[i][j] += av[i] * bv[j];
    }
    const float min_d = -3.0701134573253940f;
    const float max_d = -15.350567286626971f;
    #pragma unroll
    for (int i = 0; i < 8; i++) {
        const int d = d0 + ty * 8 + i;
        const float delta = fabsf(min_d + (max_d - min_d) * (float)d * (1.0f / (D - 1)));
        #pragma unroll
        for (int j = 0; j < 8; j++) {
            const int l = l0 + tx * 8 + j;
            const float t = (float)l * (1.0f / (L - 1));
            g_k[(size_t)d * L + l] = acc[i][j] * expf(-t * delta);
        }
    }
}

// ---------------- 4096-pt radix-4 Stockham FFT (6 fused passes) ----------------
__device__ __forceinline__ float2* fft4096_r4(float2* buf0, float2* buf1, const float2* tw,
                                              int tid, int T) {
    float2* src = buf0;
    float2* dst = buf1;
    int ls = 0;
    #pragma unroll
    for (int pass = 0; pass < 6; pass++) {
        const int s = 1 << ls;
        for (int x = tid; x < NFFT / 4; x += T) {
            const int ps = x & ~(s - 1);
            const float2 w1 = tw[ps];
            const float2 w2 = tw[2 * ps];
            float2 a = src[x];
            float2 b = src[x + 2048];
            float2 c = src[x + 1024];
            float2 d = src[x + 3072];
            float2 u0 = make_float2(a.x + b.x, a.y + b.y);
            float2 t1 = make_float2(a.x - b.x, a.y - b.y);
            float2 u1 = cmul(t1, w1);
            float2 v0 = make_float2(c.x + d.x, c.y + d.y);
            float2 t2 = make_float2(c.x - d.x, c.y - d.y);
            float2 t2w = cmul(t2, w1);
            float2 v1 = make_float2(t2w.y, -t2w.x);
            const int base = x + 3 * ps;
            dst[base]         = make_float2(u0.x + v0.x, u0.y + v0.y);
            dst[base + 2 * s] = cmul(make_float2(u0.x - v0.x, u0.y - v0.y), w2);
            dst[base + s]     = make_float2(u1.x + v1.x, u1.y + v1.y);
            dst[base + 3 * s] = cmul(make_float2(u1.x - v1.x, u1.y - v1.y), w2);
        }
        __syncthreads();
        float2* tp = src; src = dst; dst = tp;
        ls += 2;
    }
    return src;
}

__device__ __forceinline__ void build_tw(float2* tw, int tid, int T) {
    for (int j = tid; j < NFFT / 2; j += T) {
        float a = -6.283185307179586f * (float)j * (1.0f / NFFT);
        float sn, cs;
        sincosf(a, &sn, &cs);
        tw[j] = make_float2(cs, sn);
    }
}

__global__ void kf_kernel() {
    extern __shared__ float2 shf[];
    float2* A = shf;
    float2* Btmp = shf + NFFT;
    float2* tw = shf + 2 * NFFT;
    const int d = blockIdx.x;
    const int tid = threadIdx.x;
    const int T = blockDim.x;
    build_tw(tw, tid, T);
    const float* kr = g_k + (size_t)d * L;
    for (int i = tid; i < L; i += T) {
        A[i]     = make_float2(kr[i], 0.f);
        A[i + L] = make_float2(0.f, 0.f);
    }
    __syncthreads();
    float2* R = fft4096_r4(A, Btmp, tw, tid, T);
    for (int i = tid; i < NFFT; i += T) g_Kf[(size_t)d * NFFT + i] = R[i];
}

// ---------------- rmsnorm -> single fp16 ----------------
__global__ void rmsnorm_h_kernel(const float* __restrict__ x, const float* __restrict__ w,
                                 __half* __restrict__ oh) {
    const int row = blockIdx.x;
    const int tid = threadIdx.x;
    const int lane = tid & 31;
    const int wrp = tid >> 5;
    const float4* xr = (const float4*)(x + (size_t)row * D);
    float4 v = xr[tid];
    float s = v.x * v.x + v.y * v.y + v.z * v.z + v.w * v.w;
    #pragma unroll
    for (int off = 16; off > 0; off >>= 1) s += __shfl_xor_sync(0xFFFFFFFF, s, off);
    __shared__ float red[8];
    if (lane == 0) red[wrp] = s;
    __syncthreads();
    if (wrp == 0) {
        float r = (lane < 8) ? red[lane] : 0.f;
        #pragma unroll
        for (int off = 4; off > 0; off >>= 1) r += __shfl_xor_sync(0xFFFFFFFF, r, off);
        if (lane == 0) red[0] = r;
    }
    __syncthreads();
    float scale = rsqrtf(red[0] * (1.0f / D) + 1e-8f);
    float4 wv = ((const float4*)w)[tid];
    ((__half2*)(oh + (size_t)row * D))[tid * 2 + 0] =
        __floats2half2_rn(v.x * scale * wv.x, v.y * scale * wv.y);
    ((__half2*)(oh + (size_t)row * D))[tid * 2 + 1] =
        __floats2half2_rn(v.z * scale * wv.z, v.w * scale * wv.w);
}

// ---------------- weight split fp32 -> fp16 hi/lo ----------------
__global__ void wsplit_h_kernel(const float* __restrict__ w, __half* __restrict__ wh,
                                __half* __restrict__ wl, int n4) {
    int i = blockIdx.x * 256 + threadIdx.x;
    if (i < n4) {
        float4 v = ((const float4*)w)[i];
        __half hx = __float2half_rn(v.x), hy = __float2half_rn(v.y);
        __half hz = __float2half_rn(v.z), hw = __float2half_rn(v.w);
        ((__half2*)wh)[i * 2 + 0] = __halves2half2(hx, hy);
        ((__half2*)wh)[i * 2 + 1] = __halves2half2(hz, hw);
        ((__half2*)wl)[i * 2 + 0] = __halves2half2(__float2half_rn(v.x - __half2float(hx)),
                                                   __float2half_rn(v.y - __half2float(hy)));
        ((__half2*)wl)[i * 2 + 1] = __halves2half2(__float2half_rn(v.z - __half2float(hz)),
                                                   __float2half_rn(v.w - __half2float(hw)));
    }
}

// ---------------- weight convert fp32 -> single fp16 ----------------
__global__ void wconv_h_kernel(const float* __restrict__ w, __half* __restrict__ wh, int n4) {
    int i = blockIdx.x * 256 + threadIdx.x;
    if (i < n4) {
        float4 v = ((const float4*)w)[i];
        ((__half2*)wh)[i * 2 + 0] = __floats2half2_rn(v.x, v.y);
        ((__half2*)wh)[i * 2 + 1] = __floats2half2_rn(v.z, v.w);
    }
}

__device__ __forceinline__ float gelu_tanh(float x) {
    float c = 0.7978845608028654f * (x + 0.044715f * x * x * x);
    return 0.5f * x * (1.0f + tanhf(c));
}

#define BK 32
#define SROW 80
#define TILE_A_B (128 * SROW)         // 10240
#define TILE_W_B (64 * SROW)          // 5120
#define STAGE_B2 (TILE_A_B + 2 * TILE_W_B)   // 20480
#define STAGE_B1 (TILE_A_B + TILE_W_B)       // 15360
#define NSTAGE 3

// ---------------- fp16 2-term GEMM, CTA 128x64: C = A @ (Wh+Wl)^T ----------------
// EPI: 1 = +bias+res -> fp32 ; 3 = +bias -> fp16
template <int EPI>
__global__ void __launch_bounds__(256, 3)
tgemm_h2_kernel(const __half* __restrict__ Ap,
                const __half* __restrict__ Whp, const __half* __restrict__ Wlp,
                const float* __restrict__ bias, const float* __restrict__ res,
                float* __restrict__ Cf, __half* __restrict__ Chs, int N, int K) {
    extern __shared__ char smem[];
    const uint32_t sbase = smem_u32(smem);

    const int tid = threadIdx.x;
    const int wid = tid >> 5;
    const int lane = tid & 31;
    const int wm = wid & 1;
    const int wn = wid >> 1;
    const int g = lane >> 2;
    const int t = lane & 3;
    const int bm = blockIdx.y * 128;
    const int bn = blockIdx.x * 64;
    const int NC = K / BK;

    const uint32_t a_off = (uint32_t)(wm * 64 + (lane & 15)) * SROW + ((lane & 16) ? 16u : 0u);
    const uint32_t b_off = (uint32_t)(wn * 16 + ((lane >> 4) << 3) + (lane & 7)) * SROW
                         + (((lane >> 3) & 1) ? 16u : 0u);

    auto load_chunk = [&](int ck, int st) {
        const int k0 = ck * BK;
        const uint32_t stage = sbase + st * STAGE_B2;
        #pragma unroll
        for (int j = 0; j < 4; j++) {
            const int idx = j * 256 + tid;
            const int r = idx >> 2;
            const int ch = idx & 3;
            const __half* src;
            uint32_t dst;
            if (r < 128) {
                src = Ap + (size_t)(bm + r) * K + k0 + ch * 8;
                dst = stage + r * SROW + ch * 16;
            } else if (r < 192) {
                src = Whp + (size_t)(bn + r - 128) * K + k0 + ch * 8;
                dst = stage + TILE_A_B + (r - 128) * SROW + ch * 16;
            } else {
                src = Wlp + (size_t)(bn + r - 192) * K + k0 + ch * 8;
                dst = stage + TILE_A_B + TILE_W_B + (r - 192) * SROW + ch * 16;
            }
            cp_async16(dst, src);
        }
        CP_COMMIT();
    };

    float acc[4][2][4];
    #pragma unroll
    for (int mi = 0; mi < 4; mi++)
        #pragma unroll
        for (int ni = 0; ni < 2; ni++)
            #pragma unroll
            for (int q = 0; q < 4; q++) acc[mi][ni][q] = 0.f;

    load_chunk(0, 0);
    load_chunk(1, 1);

    int st = 0;
    for (int ck = 0; ck < NC; ck++) {
        cp_wait<1>();
        __syncthreads();
        if (ck + 2 < NC) load_chunk(ck + 2, (st + 2) % NSTAGE);

        const uint32_t stage = sbase + st * STAGE_B2;
        const uint32_t sA  = stage + a_off;
        const uint32_t sWh = stage + TILE_A_B + b_off;
        const uint32_t sWl = stage + TILE_A_B + TILE_W_B + b_off;

        #pragma unroll
        for (int ks = 0; ks < 2; ks++) {
            const uint32_t kb = ks * 32;

            uint32_t bh[2][2], bl[2][2];
            ldsm_x4(bh[0][0], bh[0][1], bh[1][0], bh[1][1], sWh + kb);
            ldsm_x4(bl[0][0], bl[0][1], bl[1][0], bl[1][1], sWl + kb);

            uint32_t af[4][4];
            #pragma unroll
            for (int mi = 0; mi < 4; mi++)
                ldsm_x4(af[mi][0], af[mi][1], af[mi][2], af[mi][3],
                        sA + (uint32_t)(mi * 16) * SROW + kb);
            #pragma unroll
            for (int mi = 0; mi < 4; mi++)
                #pragma unroll
                for (int ni = 0; ni < 2; ni++) mma_fp16(acc[mi][ni], af[mi], bh[ni]);
            #pragma unroll
            for (int mi = 0; mi < 4; mi++)
                #pragma unroll
                for (int ni = 0; ni < 2; ni++) mma_fp16(acc[mi][ni], af[mi], bl[ni]);
        }
        st = (st + 1) % NSTAGE;
    }

    #pragma unroll
    for (int mi = 0; mi < 4; mi++) {
        const int row0 = bm + wm * 64 + mi * 16 + g;
        #pragma unroll
        for (int ni = 0; ni < 2; ni++) {
            const int col = bn + wn * 16 + ni * 8 + 2 * t;
            const float b0 = __ldg(&bias[col]);
            const float b1 = __ldg(&bias[col + 1]);
            float v0 = acc[mi][ni][0] + b0;
            float v1 = acc[mi][ni][1] + b1;
            float v2 = acc[mi][ni][2] + b0;
            float v3 = acc[mi][ni][3] + b1;
            if (EPI == 1) {
                const float2 r0 = *(const float2*)&res[(size_t)row0 * N + col];
                const float2 r1 = *(const float2*)&res[(size_t)(row0 + 8) * N + col];
                *(float2*)&Cf[(size_t)row0 * N + col] = make_float2(v0 + r0.x, v1 + r0.y);
                *(float2*)&Cf[(size_t)(row0 + 8) * N + col] = make_float2(v2 + r1.x, v3 + r1.y);
            } else {
                *(__half2*)&Chs[(size_t)row0 * N + col] = __floats2half2_rn(v0, v1);
                *(__half2*)&Chs[(size_t)(row0 + 8) * N + col] = __floats2half2_rn(v2, v3);
            }
        }
    }
}

// ---------------- fp16 1-term GEMM, CTA 128x64: C = A @ Wh^T ----------------
// EPI: 1 = +bias+res -> fp32 ; 2 = gelu(+bias) -> fp16
template <int EPI>
__global__ void __launch_bounds__(256, 3)
tgemm_h1_kernel(const __half* __restrict__ Ap, const __half* __restrict__ Whp,
                const float* __restrict__ bias, const float* __restrict__ res,
                float* __restrict__ Cf, __half* __restrict__ Chs, int N, int K) {
    extern __shared__ char smem[];
    const uint32_t sbase = smem_u32(smem);

    const int tid = threadIdx.x;
    const int wid = tid >> 5;
    const int lane = tid & 31;
    const int wm = wid & 1;
    const int wn = wid >> 1;
    const int g = lane >> 2;
    const int t = lane & 3;
    const int bm = blockIdx.y * 128;
    const int bn = blockIdx.x * 64;
    const int NC = K / BK;

    const uint32_t a_off = (uint32_t)(wm * 64 + (lane & 15)) * SROW + ((lane & 16) ? 16u : 0u);
    const uint32_t b_off = (uint32_t)(wn * 16 + ((lane >> 4) << 3) + (lane & 7)) * SROW
                         + (((lane >> 3) & 1) ? 16u : 0u);

    auto load_chunk = [&](int ck, int st) {
        const int k0 = ck * BK;
        const uint32_t stage = sbase + st * STAGE_B1;
        #pragma unroll
        for (int j = 0; j < 3; j++) {
            const int idx = j * 256 + tid;     // 0..767
            const int r = idx >> 2;            // 0..191
            const int ch = idx & 3;
            const __half* src;
            uint32_t dst;
            if (r < 128) {
                src = Ap + (size_t)(bm + r) * K + k0 + ch * 8;
                dst = stage + r * SROW + ch * 16;
            } else {
                src = Whp + (size_t)(bn + r - 128) * K + k0 + ch * 8;
                dst = stage + TILE_A_B + (r - 128) * SROW + ch * 16;
            }
            cp_async16(dst, src);
        }
        CP_COMMIT();
    };

    float acc[4][2][4];
    #pragma unroll
    for (int mi = 0; mi < 4; mi++)
        #pragma unroll
        for (int ni = 0; ni < 2; ni++)
            #pragma unroll
            for (int q = 0; q < 4; q++) acc[mi][ni][q] = 0.f;

    load_chunk(0, 0);
    load_chunk(1, 1);

    int st = 0;
    for (int ck = 0; ck < NC; ck++) {
        cp_wait<1>();
        __syncthreads();
        if (ck + 2 < NC) load_chunk(ck + 2, (st + 2) % NSTAGE);

        const uint32_t stage = sbase + st * STAGE_B1;
        const uint32_t sA  = stage + a_off;
        const uint32_t sWh = stage + TILE_A_B + b_off;

        #pragma unroll
        for (int ks = 0; ks < 2; ks++) {
            const uint32_t kb = ks * 32;

            uint32_t bh[2][2];
            ldsm_x4(bh[0][0], bh[0][1], bh[1][0], bh[1][1], sWh + kb);

            uint32_t af[4][4];
            #pragma unroll
            for (int mi = 0; mi < 4; mi++)
                ldsm_x4(af[mi][0], af[mi][1], af[mi][2], af[mi][3],
                        sA + (uint32_t)(mi * 16) * SROW + kb);
            #pragma unroll
            for (int mi = 0; mi < 4; mi++)
                #pragma unroll
                for (int ni = 0; ni < 2; ni++) mma_fp16(acc[mi][ni], af[mi], bh[ni]);
        }
        st = (st + 1) % NSTAGE;
    }

    #pragma unroll
    for (int mi = 0; mi < 4; mi++) {
        const int row0 = bm + wm * 64 + mi * 16 + g;
        #pragma unroll
        for (int ni = 0; ni < 2; ni++) {
            const int col = bn + wn * 16 + ni * 8 + 2 * t;
            const float b0 = __ldg(&bias[col]);
            const float b1 = __ldg(&bias[col + 1]);
            float v0 = acc[mi][ni][0] + b0;
            float v1 = acc[mi][ni][1] + b1;
            float v2 = acc[mi][ni][2] + b0;
            float v3 = acc[mi][ni][3] + b1;
            if (EPI == 1) {
                const float2 r0 = *(const float2*)&res[(size_t)row0 * N + col];
                const float2 r1 = *(const float2*)&res[(size_t)(row0 + 8) * N + col];
                *(float2*)&Cf[(size_t)row0 * N + col] = make_float2(v0 + r0.x, v1 + r0.y);
                *(float2*)&Cf[(size_t)(row0 + 8) * N + col] = make_float2(v2 + r1.x, v3 + r1.y);
            } else {
                *(__half2*)&Chs[(size_t)row0 * N + col] =
                    __floats2half2_rn(gelu_tanh(v0), gelu_tanh(v1));
                *(__half2*)&Chs[(size_t)(row0 + 8) * N + col] =
                    __floats2half2_rn(gelu_tanh(v2), gelu_tanh(v3));
            }
        }
    }
}

// ---------------- short depthwise causal conv (k=3) + gate prep (fp16 input) ----------------
__global__ void shortfilter_kernel(const __half* __restrict__ u, const float* __restrict__ sw,
                                   const float* __restrict__ sb) {
    __shared__ float su[3][34][33];
    __shared__ float st0[32][33];
    __shared__ float st1[32][33];
    const int b  = blockIdx.z;
    const int d0 = blockIdx.y * 32;
    const int l0 = blockIdx.x * 32;
    const int tx = threadIdx.x;
    const int ty = threadIdx.y;
    const __half* ub = u + (size_t)b * L * 3 * D;

    #pragma unroll
    for (int grp = 0; grp < 3; grp++) {
        int c = grp * D + d0 + tx;
        {
            int l = l0 - 2 + ty;
            su[grp][ty][tx] = (l >= 0) ? __half2float(ub[(size_t)l * 3 * D + c]) : 0.f;
        }
        if (ty < 2) {
            int r = 32 + ty;
            int l = l0 - 2 + r;
            su[grp][r][tx] = __half2float(ub[(size_t)l * 3 * D + c]);
        }
    }
    __syncthreads();

    float a[3];
    #pragma unroll
    for (int grp = 0; grp < 3; grp++) {
        int c = grp * D + d0 + tx;
        float w0 = sw[c * 3 + 0], w1 = sw[c * 3 + 1], w2 = sw[c * 3 + 2];
        a[grp] = w0 * su[grp][ty][tx] + w1 * su[grp][ty + 1][tx] + w2 * su[grp][ty + 2][tx] + sb[c];
    }
    st0[ty][tx] = a[0];
    st1[ty][tx] = a[2] * a[1];
    __syncthreads();

    size_t o = ((size_t)b * D + (d0 + ty)) * L + l0 + tx;
    g_x0[o] = st0[tx][ty];
    g_vx[o] = st1[tx][ty];
}

// ---------------- fused FFT conv: 2 real channels packed per complex FFT ----------------
__global__ void conv_gate2_kernel(const float* __restrict__ fbias) {
    extern __shared__ float2 shf[];
    float2* A = shf;
    float2* Btmp = shf + NFFT;
    float2* tw = shf + 2 * NFFT;
    const int bp = blockIdx.x;
    const int pair = bp & (D / 2 - 1);
    const int b = bp / (D / 2);
    const int d0 = pair * 2;
    const int d1 = d0 + 1;
    const int tid = threadIdx.x;
    const int T = blockDim.x;

    build_tw(tw, tid, T);
    const float* v0 = g_vx + ((size_t)b * D + d0) * L;
    const float* v1 = g_vx + ((size_t)b * D + d1) * L;
    for (int i = tid; i < L; i += T) {
        A[i]     = make_float2(v0[i], v1[i]);
        A[i + L] = make_float2(0.f, 0.f);
    }
    __syncthreads();
    float2* R = fft4096_r4(A, Btmp, tw, tid, T);

    const float2* kf0 = g_Kf + (size_t)d0 * NFFT;
    const float2* kf1 = g_Kf + (size_t)d1 * NFFT;
    const float inv = 1.0f / NFFT;
    const int half = NFFT / 2;
    for (int k = tid; k <= half; k += T) {
        const int km = (NFFT - k) & (NFFT - 1);
        const float2 z1 = R[k];
        const float2 z2 = R[km];
        const float v1r = 0.5f * (z1.x + z2.x), v1i = 0.5f * (z1.y - z2.y);
        const float dr  = 0.5f * (z1.x - z2.x), di  = 0.5f * (z1.y + z2.y);
        const float v2r = di, v2i = -dr;
        const float2 k1 = kf0[k], k2 = kf1[k];
        const float y1r = (v1r * k1.x - v1i * k1.y) * inv;
        const float y1i = (v1r * k1.y + v1i * k1.x) * inv;
        const float y2r = (v2r * k2.x - v2i * k2.y) * inv;
        const float y2i = (v2r * k2.y + v2i * k2.x) * inv;
        R[k]  = make_float2(y1r - y2i, -(y1i + y2r));
        if (km != k) R[km] = make_float2(y1r + y2i, y1i - y2r);
    }
    __syncthreads();
    float2* other = (R == A) ? Btmp : A;
    float2* R2 = fft4096_r4(R, other, tw, tid, T);

    const float b0 = fbias[d0];
    const float b1 = fbias[d1];
    const float* x00 = g_x0 + ((size_t)b * D + d0) * L;
    const float* x01 = g_x0 + ((size_t)b * D + d1) * L;
    float* y0 = g_yt + ((size_t)b * D + d0) * L;
    float* y1 = g_yt + ((size_t)b * D + d1) * L;
    for (int i = tid; i < L; i += T) {
        y0[i] = (R2[i].x + v0[i] * b0) * x00[i];
        y1[i] = (-R2[i].y + v1[i] * b1) * x01[i];
    }
}

// ---------------- transpose (B,D,L) -> (B,L,D) -> single fp16 ----------------
__global__ void transconv_kernel() {
    __shared__ float t[32][33];
    const int l0 = blockIdx.x * 32;
    const int d0 = blockIdx.y * 32;
    const int b  = blockIdx.z;
    const int tx = threadIdx.x;
    const int ty = threadIdx.y;   // 0..7
    #pragma unroll
    for (int i = 0; i < 4; i++)
        t[ty + i * 8][tx] = g_yt[((size_t)b * D + d0 + ty + i * 8) * L + l0 + tx];
    __syncthreads();
    #pragma unroll
    for (int i = 0; i < 4; i++) {
        int l = l0 + ty + i * 8;
        int d = d0 + tx;
        g_g16[((size_t)b * L + l) * D + d] = __float2half_rn(t[tx][ty + i * 8]);
    }
}

// ---------------- launch ----------------
extern "C" void kernel_launch(void* const* d_in, const int* in_sizes, int n_in,
                              void* d_out, int out_size) {
    const float* x    = (const float*)d_in[0];
    const float* nin  = (const float*)d_in[1];
    const float* ipw  = (const float*)d_in[2];
    const float* ipb  = (const float*)d_in[3];
    const float* sfw  = (const float*)d_in[4];
    const float* sfb  = (const float*)d_in[5];
    const float* w1   = (const float*)d_in[6];
    const float* b1   = (const float*)d_in[7];
    const float* f1   = (const float*)d_in[8];
    const float* w2   = (const float*)d_in[9];
    const float* b2   = (const float*)d_in[10];
    const float* f2   = (const float*)d_in[11];
    const float* w3   = (const float*)d_in[12];
    const float* fbias= (const float*)d_in[13];
    const float* opw  = (const float*)d_in[14];
    const float* opb  = (const float*)d_in[15];
    const float* nw   = (const float*)d_in[16];
    const float* fw1  = (const float*)d_in[17];
    const float* fb1  = (const float*)d_in[18];
    const float* fw2  = (const float*)d_in[19];
    const float* fb2  = (const float*)d_in[20];
    float* out = (float*)d_out;

    const int fft_smem = NFFT * 2 * sizeof(float2) + (NFFT / 2) * sizeof(float2);  // 80 KB
    const int gemm2_smem = NSTAGE * STAGE_B2;    // 61440
    const int gemm1_smem = NSTAGE * STAGE_B1;    // 46080
    const int fproj_smem = 2 * 128 * 65 * sizeof(float);  // 66560
    cudaFuncSetAttribute(kf_kernel, cudaFuncAttributeMaxDynamicSharedMemorySize, fft_smem);
    cudaFuncSetAttribute(conv_gate2_kernel, cudaFuncAttributeMaxDynamicSharedMemorySize, fft_smem);
    cudaFuncSetAttribute(tgemm_h2_kernel<1>, cudaFuncAttributeMaxDynamicSharedMemorySize, gemm2_smem);
    cudaFuncSetAttribute(tgemm_h2_kernel<3>, cudaFuncAttributeMaxDynamicSharedMemorySize, gemm2_smem);
    cudaFuncSetAttribute(tgemm_h1_kernel<1>, cudaFuncAttributeMaxDynamicSharedMemorySize, gemm1_smem);
    cudaFuncSetAttribute(tgemm_h1_kernel<2>, cudaFuncAttributeMaxDynamicSharedMemorySize, gemm1_smem);
    cudaFuncSetAttribute(filter_proj_kernel, cudaFuncAttributeMaxDynamicSharedMemorySize, fproj_smem);

    float *h;
    __half *u16, *xn16, *g16, *hn16, *f1s;
    __half *wiph, *wipl, *woph, *wopl, *wf1h, *wf2h;
    cudaGetSymbolAddress((void**)&u16, g_u16);
    cudaGetSymbolAddress((void**)&h, g_h);
    cudaGetSymbolAddress((void**)&xn16, g_xn16);
    cudaGetSymbolAddress((void**)&g16, g_g16);
    cudaGetSymbolAddress((void**)&hn16, g_hn16);
    cudaGetSymbolAddress((void**)&f1s, g_f1s);
    cudaGetSymbolAddress((void**)&wiph, g_wiph); cudaGetSymbolAddress((void**)&wipl, g_wipl);
    cudaGetSymbolAddress((void**)&woph, g_woph); cudaGetSymbolAddress((void**)&wopl, g_wopl);
    cudaGetSymbolAddress((void**)&wf1h, g_wf1h);
    cudaGetSymbolAddress((void**)&wf2h, g_wf2h);

    // launch 0-2: prep; launch 3: in_proj GEMM
    wsplit_h_kernel<<<(3 * D * D / 4 + 255) / 256, 256>>>(ipw, wiph, wipl, 3 * D * D / 4);
    rmsnorm_h_kernel<<<M_ROWS, 256>>>(x, nin, xn16);
    filter_h2_kernel<<<L, 64>>>(w1, b1, f1, w2, b2, f2);
    tgemm_h2_kernel<3><<<dim3(3 * D / 64, M_ROWS / 128), 256, gemm2_smem>>>(
        xn16, wiph, wipl, ipb, nullptr, nullptr, u16, 3 * D, D);

    // filter construction
    filter_proj_kernel<<<dim3(D / 128, L / 128), 256, fproj_smem>>>(w3);
    kf_kernel<<<D, 512, fft_smem>>>();

    // short filter + gating split
    shortfilter_kernel<<<dim3(L / 32, D / 32, B), dim3(32, 32)>>>(u16, sfw, sfb);

    // long conv via packed FFT + gate, then transpose -> fp16
    conv_gate2_kernel<<<B * D / 2, 512, fft_smem>>>(fbias);
    transconv_kernel<<<dim3(L / 32, D / 32, B), dim3(32, 8)>>>();

    // out_proj + residual (fp16x2)
    wsplit_h_kernel<<<(D * D / 4 + 255) / 256, 256>>>(opw, woph, wopl, D * D / 4);
    tgemm_h2_kernel<1><<<dim3(D / 64, M_ROWS / 128), 256, gemm2_smem>>>(
        g16, woph, wopl, opb, x, h, nullptr, D, D);

    // FFN (fp16 1-term)
    rmsnorm_h_kernel<<<M_ROWS, 256>>>(h, nw, hn16);
    wconv_h_kernel<<<(2 * D * D / 4 + 255) / 256, 256>>>(fw1, wf1h, 2 * D * D / 4);
    tgemm_h1_kernel<2><<<dim3(2 * D / 64, M_ROWS / 128), 256, gemm1_smem>>>(
        hn16, wf1h, fb1, nullptr, nullptr, f1s, 2 * D, D);
    wconv_h_kernel<<<(D * 2 * D / 4 + 255) / 256, 256>>>(fw2, wf2h, D * 2 * D / 4);
    tgemm_h1_kernel<1><<<dim3(D / 64, M_ROWS / 128), 256, gemm1_smem>>>(
        f1s, wf2h, fb2, h, out, nullptr, D, 2 * D);
}